// round 14
// baseline (speedup 1.0000x reference)
#include <cuda_runtime.h>
#include <cuda_bf16.h>
#include <cstdint>

// Stacked-LSTM, dataflow wavefront, round 12 (clean resubmit after infra
// failure in round 13; kernel body identical to R12).
// vs R11: (a) recurrent K-chunks (4-7) computed FIRST, inter-layer wait only
// gates chunks 0-3 -> lower-layer hop hidden behind half the GEMM;
// (b) each warp builds a PRIVATE A tile (no cross-warp barriers at all;
// __syncwarp only); (c) per-warp dependency signal (count target 32).
// 128 CTAs x 512 thr. CTA = (lg, Ns); warp = (layer l = lg*8 + (wid>>1), nh).
// W (split bf16 hi/lo, cols hc*4+gate) resident in SMEM; c in registers;
// h packed u32 (bf16 hi | lo<<16) in g_hb, write-once per slot.

#define NBLK 128
#define NTHR 512
#define WS_OFF 0                  // hi [512][72]b16 ; lo at +73728
#define AS_OFF 147456             // 16 warps x 4608 B
#define DYN_BYTES 221184

__device__ unsigned g_hb[65][64][16][256];   // packed h (s, l, b, col)
__device__ unsigned g_xb[64][16][256];       // packed x (t, b, col)
__device__ int g_cnt[65][64];
__device__ unsigned g_count = 0;
__device__ unsigned g_phase = 0;

__device__ __forceinline__ uint32_t smem_u32(const void* p) {
  uint32_t a;
  asm("{ .reg .u64 t; cvta.to.shared.u64 t, %1; cvt.u32.u64 %0, t; }" : "=r"(a) : "l"(p));
  return a;
}
__device__ __forceinline__ void ldsm4(uint32_t* r, uint32_t a) {
  asm volatile("ldmatrix.sync.aligned.m8n8.x4.shared.b16 {%0,%1,%2,%3}, [%4];"
    : "=r"(r[0]), "=r"(r[1]), "=r"(r[2]), "=r"(r[3]) : "r"(a));
}
__device__ __forceinline__ void ldsm4t(uint32_t* r, uint32_t a) {
  asm volatile("ldmatrix.sync.aligned.m8n8.x4.trans.shared.b16 {%0,%1,%2,%3}, [%4];"
    : "=r"(r[0]), "=r"(r[1]), "=r"(r[2]), "=r"(r[3]) : "r"(a));
}
__device__ __forceinline__ void mma16816(float* c, const uint32_t* a, uint32_t b0, uint32_t b1) {
  asm volatile("mma.sync.aligned.m16n8k16.row.col.f32.bf16.bf16.f32 "
    "{%0,%1,%2,%3}, {%4,%5,%6,%7}, {%8,%9}, {%0,%1,%2,%3};"
    : "+f"(c[0]), "+f"(c[1]), "+f"(c[2]), "+f"(c[3])
    : "r"(a[0]), "r"(a[1]), "r"(a[2]), "r"(a[3]), "r"(b0), "r"(b1));
}
__device__ __forceinline__ int ldcg_i(const int* p) {
  int v; asm volatile("ld.global.cg.s32 %0, [%1];" : "=r"(v) : "l"(p)); return v;
}

__device__ __forceinline__ float sigf(float v) { return 1.0f / (1.0f + __expf(-v)); }
__device__ __forceinline__ float tanhfast(float v) {
  float e = __expf(2.0f * v);
  return 1.0f - 2.0f / (e + 1.0f);
}
__device__ __forceinline__ unsigned packsplit(float v) {
  const __nv_bfloat16 h = __float2bfloat16_rn(v);
  const __nv_bfloat16 lo = __float2bfloat16_rn(v - __bfloat162float(h));
  return (unsigned)__bfloat16_as_ushort(h) | ((unsigned)__bfloat16_as_ushort(lo) << 16);
}

__device__ __forceinline__ void grid_barrier(unsigned target) {
  __syncthreads();
  if (threadIdx.x == 0) {
    __threadfence();
    if (atomicAdd(&g_count, 1) == (unsigned)(NBLK - 1)) {
      atomicExch(&g_count, 0);
      __threadfence();
      atomicAdd(&g_phase, 1);
    } else {
      while (*((volatile unsigned*)&g_phase) != target) { __nanosleep(40); }
    }
    __threadfence();
  }
  __syncthreads();
}

__global__ __launch_bounds__(NTHR, 1) void lstm_df(
    const float* __restrict__ x,      // (16, 64, 256)
    const float* __restrict__ ist,    // (64, 2, 16, 256)
    const float* __restrict__ W,      // (512, 1024)
    const float* __restrict__ bias,   // (1024,)
    float* __restrict__ out)          // (16, 64, 256)
{
  extern __shared__ __align__(16) char dsm[];
  __shared__ unsigned s_base;

  const int tid = threadIdx.x;
  const int wid = tid >> 5;
  const int lane = tid & 31;
  const int p = wid >> 1;           // layer-within-CTA (0..7)
  const int nh = wid & 1;           // N-half
  const int bid = blockIdx.x;
  const int Ns = bid & 15;
  const int lg = bid >> 4;
  const int l = lg * 8 + p;
  const uint32_t sb = smem_u32(dsm);

  if (tid == 0) s_base = *((volatile unsigned*)&g_phase);
  __syncthreads();

  // ---- W hi/lo into resident SMEM: col cc = hc*4 + gate ----
  for (int e = tid; e < 512 * 64; e += NTHR) {
    const int k = e >> 6, cc = e & 63;
    const int hc = cc >> 2, g = cc & 3;
    const float w = W[k * 1024 + g * 256 + Ns * 16 + hc];
    const __nv_bfloat16 hi = __float2bfloat16_rn(w);
    const __nv_bfloat16 lo = __float2bfloat16_rn(w - __bfloat162float(hi));
    *(unsigned short*)(dsm + WS_OFF + k * 144 + cc * 2) = __bfloat16_as_ushort(hi);
    *(unsigned short*)(dsm + WS_OFF + 73728 + k * 144 + cc * 2) = __bfloat16_as_ushort(lo);
  }

  // ---- global init: h slot 0 (all layers), packed x, counters ----
  const int gtid = bid * NTHR + tid;
  for (int e = gtid; e < 64 * 16 * 256; e += NBLK * NTHR) {
    const int ll = e >> 12, rm = e & 4095;
    ((unsigned*)g_hb)[e] = packsplit(ist[(ll * 2 + 1) * 4096 + rm]);
  }
  for (int e = gtid; e < 64 * 16 * 256; e += NBLK * NTHR) {
    const int t = e >> 12, b = (e >> 8) & 15, c = e & 255;
    ((unsigned*)g_xb)[e] = packsplit(x[b * 16384 + t * 256 + c]);
  }
  if (gtid < 65 * 64) ((int*)g_cnt)[gtid] = (gtid < 64) ? 32 : 0;
  grid_barrier(s_base + 1);

  // ---- register c-state ----
  const int q = lane & 3;
  const int brE = (q & 1) ? (lane >> 2) + 8 : (lane >> 2);
  float cst[4];
  #pragma unroll
  for (int nt = 0; nt < 4; ++nt)
    cst[nt] = ist[(l * 2 + 0) * 4096 + brE * 256 + Ns * 16 + nh * 8 + nt * 2 + (q >> 1)];

  // ldmatrix lane offsets; PRIVATE per-warp A buffer
  const uint32_t loff = (uint32_t)((lane & 15) * 144 + (lane >> 4) * 16);
  const uint32_t aB = sb + AS_OFF + wid * 4608 + loff;
  const uint32_t bB = sb + WS_OFF + loff + nh * 64;            // + ch*9216 + ks*2304
  char* const aS = dsm + AS_OFF + wid * 4608;

  // A-build map (32 lanes, full 16x64 chunk): i-th uint4 -> row i*2+(lane>>4), c4 = lane&15
  const int arow = lane >> 4;           // 0..1 (+2i)
  const int ac4 = lane & 15;

  // ---- t-loop (dataflow, chunk order 4..7 then 0..3) ----
  for (int t = 0; t < 64; ++t) {
    // own-layer wait: h(t-1, l) complete (slot t)
    while (ldcg_i(&g_cnt[t][l]) < 32) __nanosleep(30);
    __threadfence();

    const unsigned* slow = (l == 0) ? &g_xb[t][0][0] : &g_hb[t + 1][l - 1][0][0];
    const unsigned* shigh = &g_hb[t][l][0][0];

    float acc[16];
    #pragma unroll
    for (int i = 0; i < 16; ++i) acc[i] = 0.0f;

    // prefetch first chunk (recurrent chunk 4 -> cols 0..63 of shigh)
    uint4 pf[8];
    #pragma unroll
    for (int i = 0; i < 8; ++i)
      pf[i] = __ldcg((const uint4*)(shigh + (arow + 2 * i) * 256 + ac4 * 4));

    #pragma unroll
    for (int ci = 0; ci < 8; ++ci) {
      const int ch = (ci < 4) ? ci + 4 : ci - 4;   // actual K-chunk

      // store prefetched chunk into private buffer (hi plane, lo plane)
      #pragma unroll
      for (int i = 0; i < 8; ++i) {
        const uint4 v = pf[i];
        const unsigned hi01 = __byte_perm(v.x, v.y, 0x5410);
        const unsigned lo01 = __byte_perm(v.x, v.y, 0x7632);
        const unsigned hi23 = __byte_perm(v.z, v.w, 0x5410);
        const unsigned lo23 = __byte_perm(v.z, v.w, 0x7632);
        const int row = arow + 2 * i;
        *(uint2*)(aS + row * 144 + ac4 * 8) = make_uint2(hi01, hi23);
        *(uint2*)(aS + 2304 + row * 144 + ac4 * 8) = make_uint2(lo01, lo23);
      }
      __syncwarp();

      // prefetch next chunk; the lower-layer wait gates only chunks 0-3
      if (ci < 7) {
        const int cn = (ci + 1 < 4) ? ci + 5 : ci - 3;
        if (ci == 3 && l > 0) {
          while (ldcg_i(&g_cnt[t + 1][l - 1]) < 32) __nanosleep(30);
          __threadfence();
        }
        const unsigned* s0 = (cn < 4) ? (slow + cn * 64) : (shigh + (cn - 4) * 64);
        #pragma unroll
        for (int i = 0; i < 8; ++i)
          pf[i] = __ldcg((const uint4*)(s0 + (arow + 2 * i) * 256 + ac4 * 4));
      }

      #pragma unroll
      for (int ks = 0; ks < 4; ++ks) {
        uint32_t ah[4], al[4], bh[8], bl[8];
        ldsm4(ah, aB + ks * 32);
        ldsm4(al, aB + 2304 + ks * 32);
        const uint32_t bk = bB + ch * 9216 + ks * 2304;
        ldsm4t(&bh[0], bk);
        ldsm4t(&bh[4], bk + 32);
        #pragma unroll
        for (int nt = 0; nt < 4; ++nt) mma16816(&acc[nt * 4], ah, bh[nt * 2], bh[nt * 2 + 1]);
        #pragma unroll
        for (int nt = 0; nt < 4; ++nt) mma16816(&acc[nt * 4], al, bh[nt * 2], bh[nt * 2 + 1]);
        ldsm4t(&bl[0], bk + 73728);
        ldsm4t(&bl[4], bk + 73728 + 32);
        #pragma unroll
        for (int nt = 0; nt < 4; ++nt) mma16816(&acc[nt * 4], ah, bl[nt * 2], bl[nt * 2 + 1]);
      }
      __syncwarp();
    }

    // ---- epilogue: bfly -> all 4 gates per thread; c in regs ----
    #pragma unroll
    for (int nt = 0; nt < 4; ++nt) {
      const float c0 = acc[nt * 4 + 0], c1 = acc[nt * 4 + 1];
      const float c2 = acc[nt * 4 + 2], c3 = acc[nt * 4 + 3];
      const float e0 = __shfl_xor_sync(0xffffffffu, c0, 1);
      const float e1 = __shfl_xor_sync(0xffffffffu, c1, 1);
      const float e2 = __shfl_xor_sync(0xffffffffu, c2, 1);
      const float e3 = __shfl_xor_sync(0xffffffffu, c3, 1);
      float zi, zj, zf, zo;
      if (!(q & 1)) { zi = c0; zj = c1; zf = e0; zo = e1; }
      else          { zi = e2; zj = e3; zf = c2; zo = c3; }
      const int hc = nh * 8 + nt * 2 + (q >> 1);
      const int m = Ns * 16 + hc;
      zi += __ldg(&bias[m]);
      zj += __ldg(&bias[256 + m]);
      zf += __ldg(&bias[512 + m]);
      zo += __ldg(&bias[768 + m]);
      const float ncv = sigf(zf + 1.0f) * cst[nt] + sigf(zi) * tanhfast(zj);
      const float nhv = sigf(zo) * tanhfast(ncv);
      cst[nt] = ncv;
      __stcg(&g_hb[t + 1][l][brE][m], packsplit(nhv));
      if (l == 63) out[(brE * 64 + t) * 256 + m] = nhv;
    }
    __threadfence();
    __syncwarp();
    if (lane == 0) atomicAdd(&g_cnt[t + 1][l], 1);
  }
}

extern "C" void kernel_launch(void* const* d_in, const int* in_sizes, int n_in,
                              void* d_out, int out_size) {
  const float* x    = (const float*)d_in[0];
  const float* ist  = (const float*)d_in[1];
  const float* W    = (const float*)d_in[2];
  const float* bias = (const float*)d_in[3];
  float* out        = (float*)d_out;
  (void)in_sizes; (void)n_in; (void)out_size;
  cudaFuncSetAttribute(lstm_df, cudaFuncAttributeMaxDynamicSharedMemorySize, DYN_BYTES);
  lstm_df<<<NBLK, NTHR, DYN_BYTES>>>(x, ist, W, bias, out);
}